// round 3
// baseline (speedup 1.0000x reference)
#include <cuda_runtime.h>
#include <cstdint>

#define NRMAX   512
#define TPB     256            // compute block: 8 warps, 32 elements/iter
#define HD      128
#define RD      64
#define EMB_STRIDE 130         // float2 stride (bank-conflict padding)
#define ELEMS   32             // elements per iteration per block
#define BMAX    65536

// persistent device scratch (no allocations allowed)
__device__ int g_count[NRMAX];
__device__ int g_offset[NRMAX];
__device__ int g_cursor[NRMAX];
__device__ int g_perm[BMAX];

// ---------- packed f32x2 helpers ----------
__device__ __forceinline__ unsigned long long pack2(float x, float y) {
    unsigned long long r;
    asm("mov.b64 %0, {%1, %2};" : "=l"(r) : "f"(x), "f"(y));
    return r;
}
__device__ __forceinline__ void ffma2(unsigned long long& d,
                                      unsigned long long a, unsigned long long b) {
    asm("fma.rn.f32x2 %0, %1, %2, %0;" : "+l"(d) : "l"(a), "l"(b));
}
__device__ __forceinline__ float2 unpack2(unsigned long long v) {
    float x, y;
    asm("mov.b64 {%0, %1}, %2;" : "=f"(x), "=f"(y) : "l"(v));
    return make_float2(x, y);
}

// ---------- pass 1: zero histogram ----------
__global__ void k_zero() { g_count[threadIdx.x] = 0; }

// ---------- pass 2: privatized histogram (32 blocks x 512 thr x 4 elem) ----------
__global__ void k_hist(const int* __restrict__ rel, int n) {
    __shared__ int sh[NRMAX];
    for (int i = threadIdx.x; i < NRMAX; i += blockDim.x) sh[i] = 0;
    __syncthreads();
    int base = blockIdx.x * blockDim.x * 4;
    #pragma unroll
    for (int k = 0; k < 4; k++) {
        int i = base + k * blockDim.x + threadIdx.x;
        if (i < n) atomicAdd(&sh[rel[i]], 1);
    }
    __syncthreads();
    for (int i = threadIdx.x; i < NRMAX; i += blockDim.x)
        if (sh[i]) atomicAdd(&g_count[i], sh[i]);
}

// ---------- pass 3: exclusive scan (single block) ----------
__global__ void k_plan(int nr) {
    __shared__ int sc[NRMAX];
    int t = threadIdx.x;
    int c = (t < nr) ? g_count[t] : 0;
    sc[t] = c; __syncthreads();
    for (int off = 1; off < NRMAX; off <<= 1) {
        int v = (t >= off) ? sc[t - off] : 0;
        __syncthreads();
        sc[t] += v;
        __syncthreads();
    }
    int excl = sc[t] - c;
    if (t < nr) { g_offset[t] = excl; g_cursor[t] = excl; }
}

// ---------- pass 4: two-level scatter (16 blocks x 1024 thr x 4 elem) ----------
__global__ void k_scatter(const int* __restrict__ rel, int n) {
    __shared__ int s_cnt[NRMAX], s_base[NRMAX];
    for (int i = threadIdx.x; i < NRMAX; i += blockDim.x) s_cnt[i] = 0;
    __syncthreads();
    int base = blockIdx.x * blockDim.x * 4;
    int rl[4], lr[4];
    #pragma unroll
    for (int k = 0; k < 4; k++) {
        int i = base + k * blockDim.x + threadIdx.x;
        if (i < n) { rl[k] = rel[i]; lr[k] = atomicAdd(&s_cnt[rl[k]], 1); }
        else rl[k] = -1;
    }
    __syncthreads();
    for (int i = threadIdx.x; i < NRMAX; i += blockDim.x)
        if (s_cnt[i]) s_base[i] = atomicAdd(&g_cursor[i], s_cnt[i]);
    __syncthreads();
    #pragma unroll
    for (int k = 0; k < 4; k++) {
        int i = base + k * blockDim.x + threadIdx.x;
        if (rl[k] >= 0) g_perm[s_base[rl[k]] + lr[k]] = i;
    }
}

// ---------- pass 5: compute — one block per relation ----------
// smem: duplicated-swizzled proj (64KB) + 32-element {src,dst} emb buffer.
// warp = 4 elements x 8 lanes; lane rq owns r = rq*8 .. rq*8+7.
__global__ __launch_bounds__(TPB, 2) void k_compute(
    const int*   __restrict__ src,
    const int*   __restrict__ dst,
    const float* __restrict__ ent,
    const float* __restrict__ relemb,
    const float* __restrict__ proj,
    float*       __restrict__ out)
{
    extern __shared__ float smem[];
    float4* s_proj4 = (float4*)smem;                       // HD*32 float4 = 64KB
    float2* s_emb   = (float2*)(smem + HD * RD * 2);       // ELEMS*EMB_STRIDE float2
    __shared__ int s_idx[ELEMS];

    int r_id  = blockIdx.x;
    int cnt   = g_count[r_id];
    if (cnt == 0) return;
    int start = g_offset[r_id];

    int tid  = threadIdx.x;
    int lane = tid & 31;
    int rq   = lane & 7;
    int g    = lane >> 3;                  // element sub-group within warp
    int warp = tid >> 5;
    int e_local = warp * 4 + g;            // 0..31
    unsigned gmask = 0xFFu << (lane & 24);

    // hoist rel_emb for this lane (constant for whole block)
    const float4* rr = (const float4*)(relemb + (size_t)r_id * RD) + rq * 2;
    float4 r0 = rr[0], r1 = rr[1];
    float rv[8] = {r0.x, r0.y, r0.z, r0.w, r1.x, r1.y, r1.z, r1.w};

    // stage duplicated + swizzled proj tile once per relation.
    // source float2 i: h = i>>5, rp = i&31 covers r = {2rp, 2rp+1}
    // dest float4 idx = h*32 + (rp&3)*8 + (rp>>2)  -> value {x,x,y,y}
    {
        const float2* p2 = (const float2*)(proj + (size_t)r_id * (HD * RD));
        #pragma unroll
        for (int i = tid; i < HD * (RD / 2); i += TPB) {
            float2 v = p2[i];
            int h = i >> 5, rp = i & 31;
            s_proj4[h * 32 + (rp & 3) * 8 + (rp >> 2)] =
                make_float4(v.x, v.x, v.y, v.y);
        }
    }

    int n_it = (cnt + ELEMS - 1) / ELEMS;
    int e_stage = tid >> 3;                 // staging: 8 threads per element
    int sub     = tid & 7;

    for (int it = 0; it < n_it; ++it) {
        // wait for previous iteration's readers
        if (it) __syncthreads();

        // stage 32 elements' interleaved {src,dst} embeddings
        int pos = it * ELEMS + e_stage;
        if (pos < cnt) {
            int idx = g_perm[start + pos];
            if (sub == 0) s_idx[e_stage] = idx;
            const float4* sr = (const float4*)(ent + (size_t)src[idx] * HD);
            const float4* dr = (const float4*)(ent + (size_t)dst[idx] * HD);
            float2* er = s_emb + e_stage * EMB_STRIDE;
            #pragma unroll
            for (int j = 0; j < 4; j++) {
                int q = sub * 4 + j;
                float4 sv = sr[q];
                float4 dv = dr[q];
                er[q * 4 + 0] = make_float2(sv.x, dv.x);
                er[q * 4 + 1] = make_float2(sv.y, dv.y);
                er[q * 4 + 2] = make_float2(sv.z, dv.z);
                er[q * 4 + 3] = make_float2(sv.w, dv.w);
            }
        }
        __syncthreads();

        bool active = (it * ELEMS + e_local) < cnt;
        if (active) {
            unsigned long long acc[8] = {0,0,0,0,0,0,0,0};
            const unsigned long long* er =
                (const unsigned long long*)(s_emb + e_local * EMB_STRIDE);
            const float4* pp = s_proj4 + rq;

            #pragma unroll 2
            for (int h = 0; h < HD; h++) {
                unsigned long long ed = er[h];        // {src_h, dst_h}
                float4 q0 = pp[h * 32 + 0];
                float4 q1 = pp[h * 32 + 8];
                float4 q2 = pp[h * 32 + 16];
                float4 q3 = pp[h * 32 + 24];
                ffma2(acc[0], ed, pack2(q0.x, q0.y));
                ffma2(acc[1], ed, pack2(q0.z, q0.w));
                ffma2(acc[2], ed, pack2(q1.x, q1.y));
                ffma2(acc[3], ed, pack2(q1.z, q1.w));
                ffma2(acc[4], ed, pack2(q2.x, q2.y));
                ffma2(acc[5], ed, pack2(q2.z, q2.w));
                ffma2(acc[6], ed, pack2(q3.x, q3.y));
                ffma2(acc[7], ed, pack2(q3.z, q3.w));
            }

            float s[8], d[8];
            #pragma unroll
            for (int k = 0; k < 8; k++) {
                float2 v = unpack2(acc[k]);
                s[k] = v.x; d[k] = v.y;
            }
            float ss = 0.f, dd = 0.f;
            #pragma unroll
            for (int k = 0; k < 8; k++) { ss += s[k]*s[k]; dd += d[k]*d[k]; }
            #pragma unroll
            for (int o = 4; o > 0; o >>= 1) {
                ss += __shfl_xor_sync(gmask, ss, o);
                dd += __shfl_xor_sync(gmask, dd, o);
            }
            float inv_s = 1.f / fmaxf(sqrtf(ss), 1e-12f);
            float inv_d = 1.f / fmaxf(sqrtf(dd), 1e-12f);

            float sc = 0.f;
            #pragma unroll
            for (int k = 0; k < 8; k++) {
                float df = s[k] * inv_s + rv[k] - d[k] * inv_d;
                sc += df * df;
            }
            #pragma unroll
            for (int o = 4; o > 0; o >>= 1) sc += __shfl_xor_sync(gmask, sc, o);

            if (rq == 0) out[s_idx[e_local]] = sqrtf(sc);
        }
    }
}

// ---------- launch ----------
extern "C" void kernel_launch(void* const* d_in, const int* in_sizes, int n_in,
                              void* d_out, int out_size) {
    const int*   src = (const int*)d_in[0];
    const int*   rel = (const int*)d_in[1];
    const int*   dst = (const int*)d_in[2];
    const float* ent = (const float*)d_in[3];
    const float* rle = (const float*)d_in[4];
    const float* prj = (const float*)d_in[5];
    float*       out = (float*)d_out;

    int B  = in_sizes[0];
    int NR = in_sizes[4] / RD;

    const int SMEM_BYTES = HD * RD * 2 * 4 + ELEMS * EMB_STRIDE * 8; // 64KB + 33KB
    cudaFuncSetAttribute(k_compute, cudaFuncAttributeMaxDynamicSharedMemorySize,
                         SMEM_BYTES);

    int gHist = (B + 512 * 4 - 1) / (512 * 4);       // 32
    int gScat = (B + 1024 * 4 - 1) / (1024 * 4);     // 16

    k_zero<<<1, NRMAX>>>();
    k_hist<<<gHist, 512>>>(rel, B);
    k_plan<<<1, NRMAX>>>(NR);
    k_scatter<<<gScat, 1024>>>(rel, B);
    k_compute<<<NR, TPB, SMEM_BYTES>>>(src, dst, ent, rle, prj, out);
}

// round 5
// speedup vs baseline: 1.3756x; 1.3756x over previous
#include <cuda_runtime.h>
#include <cstdint>

#define NRMAX   512
#define TPB     256
#define HD      128
#define RD      64
#define EPI     128            // elements per iteration (8 warps x 16)
#define HHALF   64
#define BMAX    65536

__device__ int g_count[NRMAX];
__device__ int g_offset[NRMAX];
__device__ int g_cursor[NRMAX];
__device__ int g_perm[BMAX];

// ---------- packed f32x2 helpers ----------
__device__ __forceinline__ unsigned long long pack2(float x, float y) {
    unsigned long long r;
    asm("mov.b64 %0, {%1, %2};" : "=l"(r) : "f"(x), "f"(y));
    return r;
}
__device__ __forceinline__ void ffma2(unsigned long long& d,
                                      unsigned long long a, unsigned long long b) {
    asm("fma.rn.f32x2 %0, %1, %2, %0;" : "+l"(d) : "l"(a), "l"(b));
}
__device__ __forceinline__ float2 unpack2(unsigned long long v) {
    float x, y;
    asm("mov.b64 {%0, %1}, %2;" : "=f"(x), "=f"(y) : "l"(v));
    return make_float2(x, y);
}

// ---------- prep ----------
__global__ void k_zero() { g_count[threadIdx.x] = 0; }

__global__ void k_hist(const int* __restrict__ rel, int n) {
    __shared__ int sh[NRMAX];
    for (int i = threadIdx.x; i < NRMAX; i += blockDim.x) sh[i] = 0;
    __syncthreads();
    int base = blockIdx.x * blockDim.x * 4;
    #pragma unroll
    for (int k = 0; k < 4; k++) {
        int i = base + k * blockDim.x + threadIdx.x;
        if (i < n) atomicAdd(&sh[rel[i]], 1);
    }
    __syncthreads();
    for (int i = threadIdx.x; i < NRMAX; i += blockDim.x)
        if (sh[i]) atomicAdd(&g_count[i], sh[i]);
}

__global__ void k_plan(int nr) {
    __shared__ int sc[NRMAX];
    int t = threadIdx.x;
    int c = (t < nr) ? g_count[t] : 0;
    sc[t] = c; __syncthreads();
    for (int off = 1; off < NRMAX; off <<= 1) {
        int v = (t >= off) ? sc[t - off] : 0;
        __syncthreads();
        sc[t] += v;
        __syncthreads();
    }
    int excl = sc[t] - c;
    if (t < nr) { g_offset[t] = excl; g_cursor[t] = excl; }
}

__global__ void k_scatter(const int* __restrict__ rel, int n) {
    __shared__ int s_cnt[NRMAX], s_base[NRMAX];
    for (int i = threadIdx.x; i < NRMAX; i += blockDim.x) s_cnt[i] = 0;
    __syncthreads();
    int base = blockIdx.x * blockDim.x * 4;
    int rl[4], lr[4];
    #pragma unroll
    for (int k = 0; k < 4; k++) {
        int i = base + k * blockDim.x + threadIdx.x;
        if (i < n) { rl[k] = rel[i]; lr[k] = atomicAdd(&s_cnt[rl[k]], 1); }
        else rl[k] = -1;
    }
    __syncthreads();
    for (int i = threadIdx.x; i < NRMAX; i += blockDim.x)
        if (s_cnt[i]) s_base[i] = atomicAdd(&g_cursor[i], s_cnt[i]);
    __syncthreads();
    #pragma unroll
    for (int k = 0; k < 4; k++) {
        int i = base + k * blockDim.x + threadIdx.x;
        if (rl[k] >= 0) g_perm[s_base[rl[k]] + lr[k]] = i;
    }
}

// ---------- compute: one block per relation, 16 elements per warp ----------
// lane = (i = lane>>3 element-quad, j = lane&7 r-group).
// lane j owns r in {4j..4j+3} u {32+4j..32+4j+3}.
// SMEM: proj[128][64] (32KB) + emb planes src/dst h-major [64][128] per half.
__global__ __launch_bounds__(TPB, 2) void k_compute(
    const int*   __restrict__ src,
    const int*   __restrict__ dst,
    const float* __restrict__ ent,
    const float* __restrict__ relemb,
    const float* __restrict__ proj,
    float*       __restrict__ out,
    int n)
{
    extern __shared__ float smem[];
    float* s_proj = smem;                              // 8192 floats
    float* s_s    = smem + HD * RD;                    // [64][128]
    float* s_d    = s_s + HHALF * EPI + 16;            // +64B skew
    __shared__ int s_idx[EPI];

    int r_id = blockIdx.x;
    int cnt  = g_count[r_id];
    if (cnt == 0) return;
    int start = g_offset[r_id];

    int tid  = threadIdx.x;
    int lane = tid & 31;
    int warp = tid >> 5;
    int j    = lane & 7;
    int i4   = lane >> 3;
    int e0   = warp * 16 + i4 * 4;                     // first of 4 elements
    unsigned gmask = 0xFFu << (lane & 24);

    // stage proj once (row-major [h][r], matches global)
    {
        const float4* p4 = (const float4*)(proj + (size_t)r_id * (HD * RD));
        float4* sp4 = (float4*)s_proj;
        #pragma unroll
        for (int t = tid; t < HD * RD / 4; t += TPB) sp4[t] = p4[t];
    }

    // rel_emb for this lane's r-sets
    const float4* rrow = (const float4*)(relemb + (size_t)r_id * RD);
    float4 rva = rrow[j];
    float4 rvb = rrow[j + 8];

    int st_e   = tid >> 1;      // staging: element
    int st_sel = tid & 1;       // 0 = src plane, 1 = dst plane

    int n_it = (cnt + EPI - 1) / EPI;
    for (int it = 0; it < n_it; ++it) {
        int pos  = it * EPI + st_e;
        int gp   = start + pos; if (gp >= n) gp = n - 1;
        int pidx = g_perm[gp];
        int node = st_sel ? dst[pidx] : src[pidx];
        const float4* erow = (const float4*)(ent + (size_t)node * HD);
        float* plane = st_sel ? s_d : s_s;

        unsigned long long accS[4][4], accD[4][4];
        #pragma unroll
        for (int e = 0; e < 4; e++)
            #pragma unroll
            for (int p = 0; p < 4; p++) { accS[e][p] = 0ull; accD[e][p] = 0ull; }

        #pragma unroll
        for (int half = 0; half < 2; ++half) {
            __syncthreads();                       // prev readers done
            if (half == 0 && st_sel == 0)
                s_idx[st_e] = (pos < cnt) ? pidx : -1;
            // stage this h-half: 16 LDG.128 + 64 STS.32 per thread
            #pragma unroll
            for (int q = 0; q < 16; q++) {
                float4 v = erow[half * 16 + q];
                plane[(q * 4 + 0) * EPI + st_e] = v.x;
                plane[(q * 4 + 1) * EPI + st_e] = v.y;
                plane[(q * 4 + 2) * EPI + st_e] = v.z;
                plane[(q * 4 + 3) * EPI + st_e] = v.w;
            }
            __syncthreads();

            const float4* pp = (const float4*)s_proj + (size_t)half * HHALF * 16;
            #pragma unroll 2
            for (int hl = 0; hl < HHALF; ++hl) {
                float4 Pa = pp[hl * 16 + j];
                float4 Pb = pp[hl * 16 + j + 8];
                unsigned long long PA0 = pack2(Pa.x, Pa.y);
                unsigned long long PA1 = pack2(Pa.z, Pa.w);
                unsigned long long PB0 = pack2(Pb.x, Pb.y);
                unsigned long long PB1 = pack2(Pb.z, Pb.w);
                float4 Sv = *(const float4*)(s_s + hl * EPI + e0);
                float4 Dv = *(const float4*)(s_d + hl * EPI + e0);
                const float sv[4] = {Sv.x, Sv.y, Sv.z, Sv.w};
                const float dv[4] = {Dv.x, Dv.y, Dv.z, Dv.w};
                #pragma unroll
                for (int e = 0; e < 4; e++) {
                    unsigned long long Se = pack2(sv[e], sv[e]);
                    unsigned long long De = pack2(dv[e], dv[e]);
                    ffma2(accS[e][0], Se, PA0);
                    ffma2(accS[e][1], Se, PA1);
                    ffma2(accS[e][2], Se, PB0);
                    ffma2(accS[e][3], Se, PB1);
                    ffma2(accD[e][0], De, PA0);
                    ffma2(accD[e][1], De, PA1);
                    ffma2(accD[e][2], De, PB0);
                    ffma2(accD[e][3], De, PB1);
                }
            }
        }

        // epilogue: 4 elements per lane, 8-lane group reduction each
        const float rva_[4] = {rva.x, rva.y, rva.z, rva.w};
        const float rvb_[4] = {rvb.x, rvb.y, rvb.z, rvb.w};
        #pragma unroll
        for (int e = 0; e < 4; e++) {
            float s[8], d[8];
            #pragma unroll
            for (int p = 0; p < 4; p++) {
                float2 a = unpack2(accS[e][p]); s[2*p] = a.x; s[2*p+1] = a.y;
                float2 b = unpack2(accD[e][p]); d[2*p] = b.x; d[2*p+1] = b.y;
            }
            float ss = 0.f, dd = 0.f;
            #pragma unroll
            for (int k = 0; k < 8; k++) { ss += s[k]*s[k]; dd += d[k]*d[k]; }
            #pragma unroll
            for (int o = 4; o > 0; o >>= 1) {
                ss += __shfl_xor_sync(gmask, ss, o);
                dd += __shfl_xor_sync(gmask, dd, o);
            }
            float inv_s = 1.f / fmaxf(sqrtf(ss), 1e-12f);
            float inv_d = 1.f / fmaxf(sqrtf(dd), 1e-12f);
            float rvk[8] = {rva_[0], rva_[1], rva_[2], rva_[3],
                            rvb_[0], rvb_[1], rvb_[2], rvb_[3]};
            float sc = 0.f;
            #pragma unroll
            for (int k = 0; k < 8; k++) {
                float df = s[k] * inv_s + rvk[k] - d[k] * inv_d;
                sc += df * df;
            }
            #pragma unroll
            for (int o = 4; o > 0; o >>= 1) sc += __shfl_xor_sync(gmask, sc, o);
            int oi = s_idx[e0 + e];
            if (j == 0 && oi >= 0) out[oi] = sqrtf(sc);
        }
    }
}

// ---------- launch ----------
extern "C" void kernel_launch(void* const* d_in, const int* in_sizes, int n_in,
                              void* d_out, int out_size) {
    const int*   src = (const int*)d_in[0];
    const int*   rel = (const int*)d_in[1];
    const int*   dst = (const int*)d_in[2];
    const float* ent = (const float*)d_in[3];
    const float* rle = (const float*)d_in[4];
    const float* prj = (const float*)d_in[5];
    float*       out = (float*)d_out;

    int B  = in_sizes[0];
    int NR = in_sizes[4] / RD;

    const int SMEM_BYTES = (HD * RD + HHALF * EPI + 16 + HHALF * EPI) * 4; // 98368
    cudaFuncSetAttribute(k_compute, cudaFuncAttributeMaxDynamicSharedMemorySize,
                         SMEM_BYTES);

    int gP = (B + 256 * 4 - 1) / (256 * 4);   // 64 blocks

    k_zero<<<1, NRMAX>>>();
    k_hist<<<gP, 256>>>(rel, B);
    k_plan<<<1, NRMAX>>>(NR);
    k_scatter<<<gP, 256>>>(rel, B);
    k_compute<<<NR, TPB, SMEM_BYTES>>>(src, dst, ent, rle, prj, out, B);
}

// round 6
// speedup vs baseline: 1.7013x; 1.2368x over previous
#include <cuda_runtime.h>
#include <cstdint>

#define NRMAX   512
#define TPB     256
#define WPB     8
#define HD      128
#define RD      64
#define WIN     16             // elements per warp-window
#define HHALF   64
#define SLICE   2080           // floats per warp slice (2x 1024 + skew, 16-aligned)
#define DSTOFF  1040           // dst plane offset within slice (64B skew vs src)
#define BMAX    65536

__device__ int g_count[NRMAX];
__device__ int g_offset[NRMAX];
__device__ int g_cursor[NRMAX];
__device__ int g_perm[BMAX];

// ---------- packed f32x2 helpers ----------
__device__ __forceinline__ unsigned long long pack2(float x, float y) {
    unsigned long long r;
    asm("mov.b64 %0, {%1, %2};" : "=l"(r) : "f"(x), "f"(y));
    return r;
}
__device__ __forceinline__ void ffma2(unsigned long long& d,
                                      unsigned long long a, unsigned long long b) {
    asm("fma.rn.f32x2 %0, %1, %2, %0;" : "+l"(d) : "l"(a), "l"(b));
}
__device__ __forceinline__ float2 unpack2(unsigned long long v) {
    float x, y;
    asm("mov.b64 {%0, %1}, %2;" : "=f"(x), "=f"(y) : "l"(v));
    return make_float2(x, y);
}

// ---------- prep ----------
__global__ void k_zero() { g_count[threadIdx.x] = 0; }

__global__ void k_hist(const int* __restrict__ rel, int n) {
    __shared__ int sh[NRMAX];
    for (int i = threadIdx.x; i < NRMAX; i += blockDim.x) sh[i] = 0;
    __syncthreads();
    int base = blockIdx.x * blockDim.x * 4;
    #pragma unroll
    for (int k = 0; k < 4; k++) {
        int i = base + k * blockDim.x + threadIdx.x;
        if (i < n) atomicAdd(&sh[rel[i]], 1);
    }
    __syncthreads();
    for (int i = threadIdx.x; i < NRMAX; i += blockDim.x)
        if (sh[i]) atomicAdd(&g_count[i], sh[i]);
}

__global__ void k_plan(int nr) {
    __shared__ int sc[NRMAX];
    int t = threadIdx.x;
    int c = (t < nr) ? g_count[t] : 0;
    sc[t] = c; __syncthreads();
    for (int off = 1; off < NRMAX; off <<= 1) {
        int v = (t >= off) ? sc[t - off] : 0;
        __syncthreads();
        sc[t] += v;
        __syncthreads();
    }
    int excl = sc[t] - c;
    if (t < nr) { g_offset[t] = excl; g_cursor[t] = excl; }
}

__global__ void k_scatter(const int* __restrict__ rel, int n) {
    __shared__ int s_cnt[NRMAX], s_base[NRMAX];
    for (int i = threadIdx.x; i < NRMAX; i += blockDim.x) s_cnt[i] = 0;
    __syncthreads();
    int base = blockIdx.x * blockDim.x * 4;
    int rl[4], lr[4];
    #pragma unroll
    for (int k = 0; k < 4; k++) {
        int i = base + k * blockDim.x + threadIdx.x;
        if (i < n) { rl[k] = rel[i]; lr[k] = atomicAdd(&s_cnt[rl[k]], 1); }
        else rl[k] = -1;
    }
    __syncthreads();
    for (int i = threadIdx.x; i < NRMAX; i += blockDim.x)
        if (s_cnt[i]) s_base[i] = atomicAdd(&g_cursor[i], s_cnt[i]);
    __syncthreads();
    #pragma unroll
    for (int k = 0; k < 4; k++) {
        int i = base + k * blockDim.x + threadIdx.x;
        if (rl[k] >= 0) g_perm[s_base[rl[k]] + lr[k]] = i;
    }
}

// ---------- compute: one block per relation; warps own 16-elem windows ----------
// lane = (i4 = lane>>3 element-quad, j = lane&7 r-group). No block syncs in loop.
__global__ __launch_bounds__(TPB, 2) void k_compute(
    const int*   __restrict__ src,
    const int*   __restrict__ dst,
    const float* __restrict__ ent,
    const float* __restrict__ relemb,
    const float* __restrict__ proj,
    float*       __restrict__ out)
{
    extern __shared__ float smem[];
    float* s_proj = smem;                     // 8192 floats (proj [h][r])
    float* s_emb  = smem + HD * RD;           // WPB * SLICE floats
    __shared__ int s_wi[WPB][WIN];

    int r_id = blockIdx.x;
    int cnt  = g_count[r_id];
    if (cnt == 0) return;
    int start = g_offset[r_id];

    int tid  = threadIdx.x;
    int lane = tid & 31;
    int warp = tid >> 5;
    int j    = lane & 7;
    int i4   = lane >> 3;
    unsigned gmask = 0xFFu << (lane & 24);

    // stage proj once (row-major [h][r])
    {
        const float4* p4 = (const float4*)(proj + (size_t)r_id * (HD * RD));
        float4* sp4 = (float4*)s_proj;
        #pragma unroll
        for (int t = tid; t < HD * RD / 4; t += TPB) sp4[t] = p4[t];
    }
    __syncthreads();

    // lane-held rel_emb
    const float4* rrow = (const float4*)(relemb + (size_t)r_id * RD);
    float4 rva = rrow[j];
    float4 rvb = rrow[j + 8];

    float* slice = s_emb + warp * SLICE;
    int e   = lane >> 1;          // staging element (0..15)
    int sel = lane & 1;           // 0=src, 1=dst

    int nwin = (cnt + WIN - 1) >> 4;
    for (int w = warp; w < nwin; w += WPB) {
        __syncwarp();             // prior epilogue done before s_wi overwrite

        int pos   = w * WIN + e;
        bool ok   = pos < cnt;
        int gp    = ok ? (start + pos) : (start + cnt - 1);
        int pidx  = g_perm[gp];
        if (sel == 0) s_wi[warp][e] = ok ? pidx : -1;
        int node  = sel ? dst[pidx] : src[pidx];
        const float4* erow = (const float4*)(ent + (size_t)node * HD);
        float* plane = slice + sel * DSTOFF;

        unsigned long long accS[4][4], accD[4][4];
        #pragma unroll
        for (int a = 0; a < 4; a++)
            #pragma unroll
            for (int p = 0; p < 4; p++) { accS[a][p] = 0ull; accD[a][p] = 0ull; }

        #pragma unroll
        for (int half = 0; half < 2; ++half) {
            __syncwarp();
            // stage 64 h-values for this (element, sel): 16 LDG.128, 64 STS.32
            #pragma unroll
            for (int q = 0; q < 16; q++) {
                float4 v = erow[half * 16 + q];
                plane[(q * 4 + 0) * WIN + e] = v.x;
                plane[(q * 4 + 1) * WIN + e] = v.y;
                plane[(q * 4 + 2) * WIN + e] = v.z;
                plane[(q * 4 + 3) * WIN + e] = v.w;
            }
            __syncwarp();

            const float4* pp = (const float4*)s_proj + (size_t)half * HHALF * 16;
            #pragma unroll 2
            for (int hl = 0; hl < HHALF; ++hl) {
                float4 Pa = pp[hl * 16 + j];
                float4 Pb = pp[hl * 16 + j + 8];
                unsigned long long PA0 = pack2(Pa.x, Pa.y);
                unsigned long long PA1 = pack2(Pa.z, Pa.w);
                unsigned long long PB0 = pack2(Pb.x, Pb.y);
                unsigned long long PB1 = pack2(Pb.z, Pb.w);
                float4 Sv = *(const float4*)(slice + hl * WIN + i4 * 4);
                float4 Dv = *(const float4*)(slice + DSTOFF + hl * WIN + i4 * 4);
                const float sv[4] = {Sv.x, Sv.y, Sv.z, Sv.w};
                const float dv[4] = {Dv.x, Dv.y, Dv.z, Dv.w};
                #pragma unroll
                for (int a = 0; a < 4; a++) {
                    unsigned long long Se = pack2(sv[a], sv[a]);
                    unsigned long long De = pack2(dv[a], dv[a]);
                    ffma2(accS[a][0], Se, PA0);
                    ffma2(accS[a][1], Se, PA1);
                    ffma2(accS[a][2], Se, PB0);
                    ffma2(accS[a][3], Se, PB1);
                    ffma2(accD[a][0], De, PA0);
                    ffma2(accD[a][1], De, PA1);
                    ffma2(accD[a][2], De, PB0);
                    ffma2(accD[a][3], De, PB1);
                }
            }
        }

        // epilogue: 4 elements per lane; reduce across 8-lane r-groups
        const float rva_[4] = {rva.x, rva.y, rva.z, rva.w};
        const float rvb_[4] = {rvb.x, rvb.y, rvb.z, rvb.w};
        #pragma unroll
        for (int a = 0; a < 4; a++) {
            float s[8], d[8];
            #pragma unroll
            for (int p = 0; p < 4; p++) {
                float2 u = unpack2(accS[a][p]); s[2*p] = u.x; s[2*p+1] = u.y;
                float2 v = unpack2(accD[a][p]); d[2*p] = v.x; d[2*p+1] = v.y;
            }
            float ss = 0.f, dd = 0.f;
            #pragma unroll
            for (int k = 0; k < 8; k++) { ss += s[k]*s[k]; dd += d[k]*d[k]; }
            #pragma unroll
            for (int o = 4; o > 0; o >>= 1) {
                ss += __shfl_xor_sync(gmask, ss, o);
                dd += __shfl_xor_sync(gmask, dd, o);
            }
            float inv_s = 1.f / fmaxf(sqrtf(ss), 1e-12f);
            float inv_d = 1.f / fmaxf(sqrtf(dd), 1e-12f);
            float rvk[8] = {rva_[0], rva_[1], rva_[2], rva_[3],
                            rvb_[0], rvb_[1], rvb_[2], rvb_[3]};
            float sc = 0.f;
            #pragma unroll
            for (int k = 0; k < 8; k++) {
                float df = s[k] * inv_s + rvk[k] - d[k] * inv_d;
                sc += df * df;
            }
            #pragma unroll
            for (int o = 4; o > 0; o >>= 1) sc += __shfl_xor_sync(gmask, sc, o);
            if (j == 0) {
                int oi = s_wi[warp][i4 * 4 + a];
                if (oi >= 0) out[oi] = sqrtf(sc);
            }
        }
    }
}

// ---------- launch ----------
extern "C" void kernel_launch(void* const* d_in, const int* in_sizes, int n_in,
                              void* d_out, int out_size) {
    const int*   src = (const int*)d_in[0];
    const int*   rel = (const int*)d_in[1];
    const int*   dst = (const int*)d_in[2];
    const float* ent = (const float*)d_in[3];
    const float* rle = (const float*)d_in[4];
    const float* prj = (const float*)d_in[5];
    float*       out = (float*)d_out;

    int B  = in_sizes[0];
    int NR = in_sizes[4] / RD;

    const int SMEM_BYTES = (HD * RD + WPB * SLICE) * 4;   // 99328
    cudaFuncSetAttribute(k_compute, cudaFuncAttributeMaxDynamicSharedMemorySize,
                         SMEM_BYTES);

    int gP = (B + 256 * 4 - 1) / (256 * 4);   // 64 blocks

    k_zero<<<1, NRMAX>>>();
    k_hist<<<gP, 256>>>(rel, B);
    k_plan<<<1, NRMAX>>>(NR);
    k_scatter<<<gP, 256>>>(rel, B);
    k_compute<<<NR, TPB, SMEM_BYTES>>>(src, dst, ent, rle, prj, out);
}

// round 9
// speedup vs baseline: 2.1335x; 1.2541x over previous
#include <cuda_runtime.h>
#include <cstdint>

#define NRMAX   512
#define MAXPER  256            // bucket capacity per relation (mean 131, +11 sigma)
#define TPB     128
#define WPB     4
#define HD      128
#define RD      64
#define WIN     16             // elements per warp-window
#define SLICE   4112           // floats: src 2048 + skew 16 + dst 2048
#define DSTOFF  2064

__device__ int g_cursor[NRMAX];
__device__ int g_perm[NRMAX * MAXPER];

// ---------- packed f32x2 helpers ----------
__device__ __forceinline__ unsigned long long pack2(float x, float y) {
    unsigned long long r;
    asm("mov.b64 %0, {%1, %2};" : "=l"(r) : "f"(x), "f"(y));
    return r;
}
__device__ __forceinline__ void ffma2(unsigned long long& d,
                                      unsigned long long a, unsigned long long b) {
    asm("fma.rn.f32x2 %0, %1, %2, %0;" : "+l"(d) : "l"(a), "l"(b));
}
__device__ __forceinline__ float2 unpack2(unsigned long long v) {
    float x, y;
    asm("mov.b64 {%0, %1}, %2;" : "=f"(x), "=f"(y) : "l"(v));
    return make_float2(x, y);
}

// ---------- pass 0: zero cursors (pure-function replay determinism) ----------
__global__ void k_zero() { g_cursor[threadIdx.x] = 0; }

// ---------- pass 1: fused privatized scatter into fixed-stride buckets ----------
__global__ void k_scatter(const int* __restrict__ rel, int n) {
    __shared__ int s_cnt[NRMAX], s_base[NRMAX];
    for (int i = threadIdx.x; i < NRMAX; i += blockDim.x) s_cnt[i] = 0;
    __syncthreads();
    int base = blockIdx.x * blockDim.x * 4;
    int rl[4], lr[4];
    #pragma unroll
    for (int k = 0; k < 4; k++) {
        int i = base + k * blockDim.x + threadIdx.x;
        if (i < n) { rl[k] = rel[i]; lr[k] = atomicAdd(&s_cnt[rl[k]], 1); }
        else rl[k] = -1;
    }
    __syncthreads();
    for (int i = threadIdx.x; i < NRMAX; i += blockDim.x)
        if (s_cnt[i]) s_base[i] = atomicAdd(&g_cursor[i], s_cnt[i]);
    __syncthreads();
    #pragma unroll
    for (int k = 0; k < 4; k++) {
        int i = base + k * blockDim.x + threadIdx.x;
        if (rl[k] >= 0) {
            int p = s_base[rl[k]] + lr[k];
            if (p < MAXPER) g_perm[rl[k] * MAXPER + p] = i;
        }
    }
}

// ---------- pass 2: compute — one block per relation, warp-owned windows ----------
// lane = (i4 = lane>>3 element-quad, j = lane&7 r-group); lane j owns
// r in {4j..4j+3} u {32+4j..32+4j+3}. Full-h staging: one gather per window.
__global__ __launch_bounds__(TPB, 2) void k_compute(
    const int*   __restrict__ src,
    const int*   __restrict__ dst,
    const float* __restrict__ ent,
    const float* __restrict__ relemb,
    const float* __restrict__ proj,
    float*       __restrict__ out)
{
    extern __shared__ float smem[];
    float* s_proj = smem;                     // 8192 floats (proj [h][r])
    float* s_emb  = smem + HD * RD;           // WPB * SLICE
    __shared__ int s_wi[WPB][WIN];

    int r_id = blockIdx.x;
    int cnt  = g_cursor[r_id];
    if (cnt > MAXPER) cnt = MAXPER;

    int tid  = threadIdx.x;
    int lane = tid & 31;
    int warp = tid >> 5;

    // stage proj (row-major [h][r])
    {
        const float4* p4 = (const float4*)(proj + (size_t)r_id * (HD * RD));
        float4* sp4 = (float4*)s_proj;
        #pragma unroll
        for (int t = tid; t < HD * RD / 4; t += TPB) sp4[t] = p4[t];
    }
    __syncthreads();
    if (cnt == 0) return;

    int j  = lane & 7;
    int i4 = lane >> 3;
    unsigned gmask = 0xFFu << (lane & 24);

    const float4* rrow = (const float4*)(relemb + (size_t)r_id * RD);
    float4 rva = rrow[j];
    float4 rvb = rrow[j + 8];

    float* slice = s_emb + warp * SLICE;
    int e   = lane >> 1;          // staging element (0..15)
    int sel = lane & 1;           // 0=src, 1=dst
    float* plane = slice + sel * DSTOFF;
    const int* g_bucket = g_perm + r_id * MAXPER;

    int nwin = (cnt + WIN - 1) >> 4;
    for (int w = warp; w < nwin; w += WPB) {
        __syncwarp();             // prior epilogue done before slice/s_wi overwrite

        int pos  = w * WIN + e;
        bool ok  = pos < cnt;
        int pidx = g_bucket[ok ? pos : (cnt - 1)];
        if (sel == 0) s_wi[warp][e] = ok ? pidx : -1;
        int node = sel ? dst[pidx] : src[pidx];
        const float4* erow = (const float4*)(ent + (size_t)node * HD);

        // gather all 128 h-values for this (element, sel): 32 LDG.128
        #pragma unroll
        for (int q = 0; q < 32; q++) {
            float4 v = erow[q];
            plane[(q * 4 + 0) * WIN + e] = v.x;
            plane[(q * 4 + 1) * WIN + e] = v.y;
            plane[(q * 4 + 2) * WIN + e] = v.z;
            plane[(q * 4 + 3) * WIN + e] = v.w;
        }
        __syncwarp();

        unsigned long long accS[4][4], accD[4][4];
        #pragma unroll
        for (int a = 0; a < 4; a++)
            #pragma unroll
            for (int p = 0; p < 4; p++) { accS[a][p] = 0ull; accD[a][p] = 0ull; }

        const float4* pp = (const float4*)s_proj;
        #pragma unroll 4
        for (int hl = 0; hl < HD; ++hl) {
            float4 Pa = pp[hl * 16 + j];
            float4 Pb = pp[hl * 16 + j + 8];
            unsigned long long PA0 = pack2(Pa.x, Pa.y);
            unsigned long long PA1 = pack2(Pa.z, Pa.w);
            unsigned long long PB0 = pack2(Pb.x, Pb.y);
            unsigned long long PB1 = pack2(Pb.z, Pb.w);
            float4 Sv = *(const float4*)(slice + hl * WIN + i4 * 4);
            float4 Dv = *(const float4*)(slice + DSTOFF + hl * WIN + i4 * 4);
            const float sv[4] = {Sv.x, Sv.y, Sv.z, Sv.w};
            const float dv[4] = {Dv.x, Dv.y, Dv.z, Dv.w};
            #pragma unroll
            for (int a = 0; a < 4; a++) {
                unsigned long long Se = pack2(sv[a], sv[a]);
                unsigned long long De = pack2(dv[a], dv[a]);
                ffma2(accS[a][0], Se, PA0);
                ffma2(accS[a][1], Se, PA1);
                ffma2(accS[a][2], Se, PB0);
                ffma2(accS[a][3], Se, PB1);
                ffma2(accD[a][0], De, PA0);
                ffma2(accD[a][1], De, PA1);
                ffma2(accD[a][2], De, PB0);
                ffma2(accD[a][3], De, PB1);
            }
        }

        // epilogue
        const float rva_[4] = {rva.x, rva.y, rva.z, rva.w};
        const float rvb_[4] = {rvb.x, rvb.y, rvb.z, rvb.w};
        #pragma unroll
        for (int a = 0; a < 4; a++) {
            float s[8], d[8];
            #pragma unroll
            for (int p = 0; p < 4; p++) {
                float2 u = unpack2(accS[a][p]); s[2*p] = u.x; s[2*p+1] = u.y;
                float2 v = unpack2(accD[a][p]); d[2*p] = v.x; d[2*p+1] = v.y;
            }
            float ss = 0.f, dd = 0.f;
            #pragma unroll
            for (int k = 0; k < 8; k++) { ss += s[k]*s[k]; dd += d[k]*d[k]; }
            #pragma unroll
            for (int o = 4; o > 0; o >>= 1) {
                ss += __shfl_xor_sync(gmask, ss, o);
                dd += __shfl_xor_sync(gmask, dd, o);
            }
            float inv_s = 1.f / fmaxf(sqrtf(ss), 1e-12f);
            float inv_d = 1.f / fmaxf(sqrtf(dd), 1e-12f);
            float rvk[8] = {rva_[0], rva_[1], rva_[2], rva_[3],
                            rvb_[0], rvb_[1], rvb_[2], rvb_[3]};
            float sc = 0.f;
            #pragma unroll
            for (int k = 0; k < 8; k++) {
                float df = s[k] * inv_s + rvk[k] - d[k] * inv_d;
                sc += df * df;
            }
            #pragma unroll
            for (int o = 4; o > 0; o >>= 1) sc += __shfl_xor_sync(gmask, sc, o);
            if (j == 0) {
                int oi = s_wi[warp][i4 * 4 + a];
                if (oi >= 0) out[oi] = sqrtf(sc);
            }
        }
    }
}

// ---------- launch ----------
extern "C" void kernel_launch(void* const* d_in, const int* in_sizes, int n_in,
                              void* d_out, int out_size) {
    const int*   src = (const int*)d_in[0];
    const int*   rel = (const int*)d_in[1];
    const int*   dst = (const int*)d_in[2];
    const float* ent = (const float*)d_in[3];
    const float* rle = (const float*)d_in[4];
    const float* prj = (const float*)d_in[5];
    float*       out = (float*)d_out;

    int B  = in_sizes[0];
    int NR = in_sizes[4] / RD;

    const int SMEM_BYTES = (HD * RD + WPB * SLICE) * 4;   // 32768 + 65792 = 98560
    cudaFuncSetAttribute(k_compute, cudaFuncAttributeMaxDynamicSharedMemorySize,
                         SMEM_BYTES);

    int gS = (B + 256 * 4 - 1) / (256 * 4);   // 64 blocks

    k_zero<<<1, NRMAX>>>();
    k_scatter<<<gS, 256>>>(rel, B);
    k_compute<<<NR, TPB, SMEM_BYTES>>>(src, dst, ent, rle, prj, out);
}